// round 1
// baseline (speedup 1.0000x reference)
#include <cuda_runtime.h>
#include <cuda_bf16.h>
#include <math.h>

// Problem shapes (fixed by the dataset)
#define T_MAX 262144
#define B_MAX 4096
#define F_DIM 128
#define H_DIM 256
#define C_DIM 512
#define KV_DIM 512

// Scratch (allocation-free rule: __device__ globals)
__device__ float g_h1[(size_t)T_MAX * H_DIM];       // 256 MB
__device__ float g_h2[(size_t)T_MAX * H_DIM];       // 256 MB
__device__ float g_kv[(size_t)T_MAX * KV_DIM];      // 512 MB
__device__ float g_q [(size_t)B_MAX * H_DIM];       // 4 MB
__device__ float g_logits[T_MAX];
__device__ int   g_segstart[B_MAX + 1];

// ---------------------------------------------------------------------------
// Classic 128x128 register-tiled SGEMM: C[M,N] = A[M,K] @ W[K,N] + bias, opt ReLU
// A row-major, W row-major. Requires M%128==0, N%128==0, K%8==0 (all hold here).
// 256 threads, each computes an 8x8 tile.
// ---------------------------------------------------------------------------
#define BM 128
#define BN 128
#define BK 8
#define TM 8
#define TN 8

template <bool RELU>
__global__ __launch_bounds__(256) void sgemm_bias(
    const float* __restrict__ A, const float* __restrict__ W,
    const float* __restrict__ bias, float* __restrict__ C,
    int M, int N, int K)
{
    __shared__ float As[BK][BM];
    __shared__ float Ws[BK][BN];

    const int bn = blockIdx.x;
    const int bm = blockIdx.y;
    const int tid = threadIdx.x;

    const float* Ab = A + (size_t)bm * BM * K;
    const float* Wb = W + (size_t)bn * BN;

    // global-load mapping
    const int aRow = tid >> 1;            // 0..127
    const int aCol = (tid & 1) * 4;       // 0 or 4
    const int wRow = tid >> 5;            // 0..7
    const int wCol = (tid & 31) * 4;      // 0..124

    // compute mapping
    const int ty = tid >> 4;              // 0..15
    const int tx = tid & 15;              // 0..15
    const int row0 = ty * TM;
    const int col0 = tx * TN;

    float acc[TM][TN];
#pragma unroll
    for (int i = 0; i < TM; i++)
#pragma unroll
        for (int j = 0; j < TN; j++) acc[i][j] = 0.f;

    for (int k0 = 0; k0 < K; k0 += BK) {
        float4 a4 = *reinterpret_cast<const float4*>(Ab + (size_t)aRow * K + k0 + aCol);
        As[aCol + 0][aRow] = a4.x;
        As[aCol + 1][aRow] = a4.y;
        As[aCol + 2][aRow] = a4.z;
        As[aCol + 3][aRow] = a4.w;
        float4 w4 = *reinterpret_cast<const float4*>(Wb + (size_t)(k0 + wRow) * N + wCol);
        *reinterpret_cast<float4*>(&Ws[wRow][wCol]) = w4;
        __syncthreads();

#pragma unroll
        for (int k = 0; k < BK; k++) {
            float am[TM], wn[TN];
#pragma unroll
            for (int i = 0; i < TM; i++) am[i] = As[k][row0 + i];
#pragma unroll
            for (int j = 0; j < TN; j++) wn[j] = Ws[k][col0 + j];
#pragma unroll
            for (int i = 0; i < TM; i++)
#pragma unroll
                for (int j = 0; j < TN; j++) acc[i][j] = fmaf(am[i], wn[j], acc[i][j]);
        }
        __syncthreads();
    }

    const int gRow = bm * BM + row0;
    const int gCol = bn * BN + col0;
#pragma unroll
    for (int j = 0; j < TN; j++) {
        float bj = bias[gCol + j];
#pragma unroll
        for (int i = 0; i < TM; i++) {
            float c = acc[i][j] + bj;
            if (RELU) c = fmaxf(c, 0.f);
            C[(size_t)(gRow + i) * N + gCol + j] = c;
        }
    }
}

// ---------------------------------------------------------------------------
// Segment starts from sorted segment_ids (every segment non-empty).
// ---------------------------------------------------------------------------
__global__ void segstart_kernel(const int* __restrict__ seg, int T, int B)
{
    int t = blockIdx.x * 256 + threadIdx.x;
    if (t == 0) {
        g_segstart[seg[0]] = 0;   // seg[0] == 0 (sorted, all segments present)
        g_segstart[B] = T;
    }
    if (t > 0 && t < T) {
        int s = seg[t];
        if (s != seg[t - 1]) g_segstart[s] = t;
    }
}

// ---------------------------------------------------------------------------
// logits[t] = dot(q[seg[t]], kv[t, 0:256]) / 16      (warp per row)
// ---------------------------------------------------------------------------
__global__ __launch_bounds__(256) void logits_kernel(const int* __restrict__ seg, int T)
{
    int t = blockIdx.x * 8 + (threadIdx.x >> 5);
    if (t >= T) return;
    int lane = threadIdx.x & 31;
    const float* krow = g_kv + (size_t)t * KV_DIM;
    const float* qrow = g_q + (size_t)seg[t] * H_DIM;
    float s = 0.f;
#pragma unroll
    for (int i = lane; i < H_DIM; i += 32) s = fmaf(krow[i], qrow[i], s);
#pragma unroll
    for (int o = 16; o; o >>= 1) s += __shfl_xor_sync(0xffffffffu, s, o);
    if (lane == 0) g_logits[t] = s * 0.0625f;   // 1/sqrt(256)
}

// ---------------------------------------------------------------------------
// Per-segment: stable softmax over logits, write w, then weighted sum of v.
// One block (256 threads == H) per segment.
// ---------------------------------------------------------------------------
__global__ __launch_bounds__(256) void segreduce_kernel(
    float* __restrict__ emb, float* __restrict__ wout)
{
    const int s = blockIdx.x;
    const int s0 = g_segstart[s];
    const int s1 = g_segstart[s + 1];
    const int tid = threadIdx.x;

    __shared__ float red[8];
    __shared__ float bcast;

    // 1) max
    float m = -INFINITY;
    for (int t = s0 + tid; t < s1; t += 256) m = fmaxf(m, g_logits[t]);
#pragma unroll
    for (int o = 16; o; o >>= 1) m = fmaxf(m, __shfl_xor_sync(0xffffffffu, m, o));
    if ((tid & 31) == 0) red[tid >> 5] = m;
    __syncthreads();
    if (tid == 0) {
        float mm = red[0];
#pragma unroll
        for (int i = 1; i < 8; i++) mm = fmaxf(mm, red[i]);
        bcast = mm;
    }
    __syncthreads();
    m = bcast;
    __syncthreads();

    // 2) sum of exp
    float z = 0.f;
    for (int t = s0 + tid; t < s1; t += 256) z += __expf(g_logits[t] - m);
#pragma unroll
    for (int o = 16; o; o >>= 1) z += __shfl_xor_sync(0xffffffffu, z, o);
    if ((tid & 31) == 0) red[tid >> 5] = z;
    __syncthreads();
    if (tid == 0) {
        float zz = 0.f;
#pragma unroll
        for (int i = 0; i < 8; i++) zz += red[i];
        bcast = zz;
    }
    __syncthreads();
    const float inv = 1.f / bcast;
    __syncthreads();

    // 3) write normalized weights
    for (int t = s0 + tid; t < s1; t += 256) wout[t] = __expf(g_logits[t] - m) * inv;
    __syncthreads();   // make wout writes visible block-wide

    // 4) weighted sum of v rows; thread tid owns hidden column tid
    float acc = 0.f;
    for (int t = s0; t < s1; t++) {
        float w = wout[t];                                   // L1 broadcast
        acc = fmaf(w, g_kv[(size_t)t * KV_DIM + H_DIM + tid], acc);
    }
    emb[(size_t)s * H_DIM + tid] = acc;
}

// ---------------------------------------------------------------------------
// Launch
// ---------------------------------------------------------------------------
extern "C" void kernel_launch(void* const* d_in, const int* in_sizes, int n_in,
                              void* d_out, int out_size)
{
    const float* objects = (const float*)d_in[0];
    const float* context = (const float*)d_in[1];
    const int*   seg     = (const int*)  d_in[2];
    const float* W1 = (const float*)d_in[3];
    const float* b1 = (const float*)d_in[4];
    const float* W2 = (const float*)d_in[5];
    const float* b2 = (const float*)d_in[6];
    const float* W3 = (const float*)d_in[7];
    const float* b3 = (const float*)d_in[8];
    const float* Wq = (const float*)d_in[9];
    const float* bq = (const float*)d_in[10];

    const int T = in_sizes[2];                 // 262144
    const int B = in_sizes[1] / C_DIM;         // 4096

    float* out = (float*)d_out;
    float* emb_out = out;                      // [B, H]
    float* w_out   = out + (size_t)B * H_DIM;  // [T]

    float *p_h1, *p_h2, *p_kv, *p_q;
    cudaGetSymbolAddress((void**)&p_h1, g_h1);
    cudaGetSymbolAddress((void**)&p_h2, g_h2);
    cudaGetSymbolAddress((void**)&p_kv, g_kv);
    cudaGetSymbolAddress((void**)&p_q,  g_q);

    // q = context @ Wq + bq    [B=4096, K=512, N=256]
    sgemm_bias<false><<<dim3(H_DIM / BN, B / BM), 256>>>(context, Wq, bq, p_q, B, H_DIM, C_DIM);
    // h1 = relu(objects @ W1 + b1)   [T, 128 -> 256]
    sgemm_bias<true ><<<dim3(H_DIM / BN, T / BM), 256>>>(objects, W1, b1, p_h1, T, H_DIM, F_DIM);
    // h2 = relu(h1 @ W2 + b2)        [T, 256 -> 256]
    sgemm_bias<true ><<<dim3(H_DIM / BN, T / BM), 256>>>(p_h1, W2, b2, p_h2, T, H_DIM, H_DIM);
    // kv = h2 @ W3 + b3              [T, 256 -> 512]
    sgemm_bias<false><<<dim3(KV_DIM / BN, T / BM), 256>>>(p_h2, W3, b3, p_kv, T, KV_DIM, H_DIM);

    segstart_kernel<<<(T + 255) / 256, 256>>>(seg, T, B);
    logits_kernel<<<T / 8, 256>>>(seg, T);
    segreduce_kernel<<<B, 256>>>(emb_out, w_out);
}

// round 3
// speedup vs baseline: 3.3258x; 3.3258x over previous
#include <cuda_runtime.h>
#include <cuda_bf16.h>
#include <math.h>
#include <stdint.h>

// Problem shapes (fixed by the dataset)
#define T_MAX 262144
#define B_MAX 4096
#define F_DIM 128
#define H_DIM 256
#define C_DIM 512
#define KV_DIM 512

// ---------------------------------------------------------------------------
// Scratch (allocation-free rule: __device__ globals)
// ---------------------------------------------------------------------------
__device__ float g_h1 [(size_t)T_MAX * H_DIM];       // 256 MB (tf32 values)
__device__ float g_h2 [(size_t)T_MAX * H_DIM];       // 256 MB (tf32 values)
__device__ float g_kv [(size_t)T_MAX * KV_DIM];      // 512 MB (fp32)
__device__ float g_q  [(size_t)B_MAX * H_DIM];       // 4 MB
__device__ float g_Wt1[H_DIM * F_DIM];               // W1^T  [N=256][K=128]
__device__ float g_Wt2[H_DIM * H_DIM];               // W2^T
__device__ float g_Wt3[KV_DIM * H_DIM];              // W3^T
__device__ float g_Wtq[H_DIM * C_DIM];               // Wq^T
__device__ float g_logits[T_MAX];
__device__ int   g_segstart[B_MAX + 1];

// ---------------------------------------------------------------------------
// Helpers
// ---------------------------------------------------------------------------
__device__ __forceinline__ uint32_t smem_u32(const void* p) {
    uint32_t a;
    asm("{ .reg .u64 t; cvta.to.shared.u64 t, %1; cvt.u32.u64 %0, t; }" : "=r"(a) : "l"(p));
    return a;
}
__device__ __forceinline__ float to_tf32(float f) {
    uint32_t u;
    asm("cvt.rna.tf32.f32 %0, %1;" : "=r"(u) : "f"(f));
    return __uint_as_float(u);
}
__device__ __forceinline__ uint32_t to_tf32_u(float f) {
    uint32_t u;
    asm("cvt.rna.tf32.f32 %0, %1;" : "=r"(u) : "f"(f));
    return u;
}

#define CP_ASYNC16(dst, src) \
    asm volatile("cp.async.cg.shared.global [%0], [%1], 16;" :: "r"(dst), "l"(src) : "memory")
#define CP_COMMIT() asm volatile("cp.async.commit_group;" ::: "memory")
#define CP_WAIT0()  asm volatile("cp.async.wait_group 0;" ::: "memory")
#define CP_WAIT1()  asm volatile("cp.async.wait_group 1;" ::: "memory")

// mma.sync m16n8k8 tf32: D = A*B + D (fp32 accumulate)
__device__ __forceinline__ void mma_tf32(float* c, const uint32_t* a, const uint32_t* b) {
    asm volatile(
        "mma.sync.aligned.m16n8k8.row.col.f32.tf32.tf32.f32 "
        "{%0,%1,%2,%3}, {%4,%5,%6,%7}, {%8,%9}, {%0,%1,%2,%3};"
        : "+f"(c[0]), "+f"(c[1]), "+f"(c[2]), "+f"(c[3])
        : "r"(a[0]), "r"(a[1]), "r"(a[2]), "r"(a[3]), "r"(b[0]), "r"(b[1]));
}

// ---------------------------------------------------------------------------
// Pipelined tf32 tensor-core GEMM: C[M,N] = A[M,K] @ Wt[N,K]^T + bias
// BM=128, BN=128, BK=16, 256 threads, warp tile 32x64, 2-stage cp.async.
// Smem rows padded to stride 20 floats -> conflict-free fragment loads.
// ---------------------------------------------------------------------------
#define STRIDE 20
#define STAGE_FLOATS (2 * 128 * STRIDE)   // A(2560) + B(2560) floats per stage

template <bool RELU, bool ROUND, bool CVT_A>
__global__ __launch_bounds__(256, 2) void gemm_tc(
    const float* __restrict__ A, const float* __restrict__ Wt,
    const float* __restrict__ bias, float* __restrict__ C,
    int M, int N, int K)
{
    __shared__ float sm[2 * STAGE_FLOATS];   // 40960 B
    const uint32_t sb = smem_u32(sm);

    const int tid  = threadIdx.x;
    const int wid  = tid >> 5;
    const int lane = tid & 31;
    const int g    = lane >> 2;              // 0..7
    const int tg   = lane & 3;               // 0..3
    const int wm   = wid >> 1;               // 0..3  (M warps)
    const int wn   = wid & 1;                // 0..1  (N warps)

    const size_t m0 = (size_t)blockIdx.y * 128;
    const size_t n0 = (size_t)blockIdx.x * 128;
    const float* Ablk = A  + m0 * K;
    const float* Bblk = Wt + n0 * K;

    // per-thread cp.async mapping: 512 float4 per tile, 2 per thread
    const int ldrow0 = tid >> 2;             // used with idx = tid, tid+256
    const int ldk4_0 = tid & 3;

    auto load_stage = [&](int s, int kblk) {
        const float* Asrc = Ablk + kblk * 16;
        const float* Bsrc = Bblk + kblk * 16;
        uint32_t abase = sb + (uint32_t)(s * STAGE_FLOATS) * 4u;
        uint32_t bbase = abase + 128 * STRIDE * 4u;
#pragma unroll
        for (int i = 0; i < 2; i++) {
            int idx = tid + i * 256;
            int row = idx >> 2, k4 = idx & 3;
            CP_ASYNC16(abase + (uint32_t)(row * STRIDE + k4 * 4) * 4u,
                       Asrc + (size_t)row * K + k4 * 4);
            CP_ASYNC16(bbase + (uint32_t)(row * STRIDE + k4 * 4) * 4u,
                       Bsrc + (size_t)row * K + k4 * 4);
        }
        CP_COMMIT();
    };

    float acc[2][8][4];
#pragma unroll
    for (int mf = 0; mf < 2; mf++)
#pragma unroll
        for (int nf = 0; nf < 8; nf++)
#pragma unroll
            for (int j = 0; j < 4; j++) acc[mf][nf][j] = 0.f;

    const int nk = K >> 4;
    load_stage(0, 0);

    for (int c = 0; c < nk; c++) {
        if (c + 1 < nk) { load_stage((c + 1) & 1, c + 1); CP_WAIT1(); }
        else            { CP_WAIT0(); }
        __syncthreads();

        const float* As = sm + (c & 1) * STAGE_FLOATS;
        const float* Bs = As + 128 * STRIDE;

#pragma unroll
        for (int ks = 0; ks < 2; ks++) {
            uint32_t a[2][4], b[8][2];
#pragma unroll
            for (int mf = 0; mf < 2; mf++) {
                int r = wm * 32 + mf * 16 + g;
                int cc = ks * 8 + tg;
                float a0 = As[r * STRIDE + cc];
                float a1 = As[(r + 8) * STRIDE + cc];
                float a2 = As[r * STRIDE + cc + 4];
                float a3 = As[(r + 8) * STRIDE + cc + 4];
                if (CVT_A) {
                    a[mf][0] = to_tf32_u(a0); a[mf][1] = to_tf32_u(a1);
                    a[mf][2] = to_tf32_u(a2); a[mf][3] = to_tf32_u(a3);
                } else {
                    a[mf][0] = __float_as_uint(a0); a[mf][1] = __float_as_uint(a1);
                    a[mf][2] = __float_as_uint(a2); a[mf][3] = __float_as_uint(a3);
                }
            }
#pragma unroll
            for (int nf = 0; nf < 8; nf++) {
                int n = wn * 64 + nf * 8 + g;
                int cc = ks * 8 + tg;
                b[nf][0] = __float_as_uint(Bs[n * STRIDE + cc]);
                b[nf][1] = __float_as_uint(Bs[n * STRIDE + cc + 4]);
            }
#pragma unroll
            for (int mf = 0; mf < 2; mf++)
#pragma unroll
                for (int nf = 0; nf < 8; nf++)
                    mma_tf32(acc[mf][nf], a[mf], b[nf]);
        }
        __syncthreads();
    }

    // Epilogue: bias (+ReLU) (+tf32 round), write float2 pairs
#pragma unroll
    for (int mf = 0; mf < 2; mf++) {
        size_t row0 = m0 + wm * 32 + mf * 16 + g;
#pragma unroll
        for (int nf = 0; nf < 8; nf++) {
            int col = (int)n0 + wn * 64 + nf * 8 + tg * 2;
            float b0 = bias[col], b1 = bias[col + 1];
            float v0 = acc[mf][nf][0] + b0;
            float v1 = acc[mf][nf][1] + b1;
            float v2 = acc[mf][nf][2] + b0;
            float v3 = acc[mf][nf][3] + b1;
            if (RELU) { v0 = fmaxf(v0, 0.f); v1 = fmaxf(v1, 0.f); v2 = fmaxf(v2, 0.f); v3 = fmaxf(v3, 0.f); }
            if (ROUND) { v0 = to_tf32(v0); v1 = to_tf32(v1); v2 = to_tf32(v2); v3 = to_tf32(v3); }
            *reinterpret_cast<float2*>(C + row0 * N + col)       = make_float2(v0, v1);
            *reinterpret_cast<float2*>(C + (row0 + 8) * N + col) = make_float2(v2, v3);
        }
    }
}

// ---------------------------------------------------------------------------
// Weight transpose + round to tf32:  Wt[n][k] = tf32(W[k][n])
// ---------------------------------------------------------------------------
__global__ void transpose_round(const float* __restrict__ W, float* __restrict__ Wt, int K, int N) {
    int i = blockIdx.x * 256 + threadIdx.x;
    if (i < K * N) {
        int k = i / N, n = i - k * N;
        Wt[(size_t)n * K + k] = to_tf32(W[i]);
    }
}

// ---------------------------------------------------------------------------
// Segment starts from sorted segment_ids (every segment non-empty).
// ---------------------------------------------------------------------------
__global__ void segstart_kernel(const int* __restrict__ seg, int T, int B)
{
    int t = blockIdx.x * 256 + threadIdx.x;
    if (t == 0) { g_segstart[seg[0]] = 0; g_segstart[B] = T; }
    if (t > 0 && t < T) {
        int s = seg[t];
        if (s != seg[t - 1]) g_segstart[s] = t;
    }
}

// logits[t] = dot(q[seg[t]], kv[t, 0:256]) / 16   (warp per row)
__global__ __launch_bounds__(256) void logits_kernel(const int* __restrict__ seg, int T)
{
    int t = blockIdx.x * 8 + (threadIdx.x >> 5);
    if (t >= T) return;
    int lane = threadIdx.x & 31;
    const float* krow = g_kv + (size_t)t * KV_DIM;
    const float* qrow = g_q + (size_t)seg[t] * H_DIM;
    float s = 0.f;
#pragma unroll
    for (int i = lane; i < H_DIM; i += 32) s = fmaf(krow[i], qrow[i], s);
#pragma unroll
    for (int o = 16; o; o >>= 1) s += __shfl_xor_sync(0xffffffffu, s, o);
    if (lane == 0) g_logits[t] = s * 0.0625f;
}

// Per-segment softmax + weighted value sum. One 256-thread block per segment.
__global__ __launch_bounds__(256) void segreduce_kernel(
    float* __restrict__ emb, float* __restrict__ wout)
{
    const int s = blockIdx.x;
    const int s0 = g_segstart[s];
    const int s1 = g_segstart[s + 1];
    const int tid = threadIdx.x;

    __shared__ float red[8];
    __shared__ float bcast;

    float m = -INFINITY;
    for (int t = s0 + tid; t < s1; t += 256) m = fmaxf(m, g_logits[t]);
#pragma unroll
    for (int o = 16; o; o >>= 1) m = fmaxf(m, __shfl_xor_sync(0xffffffffu, m, o));
    if ((tid & 31) == 0) red[tid >> 5] = m;
    __syncthreads();
    if (tid == 0) {
        float mm = red[0];
#pragma unroll
        for (int i = 1; i < 8; i++) mm = fmaxf(mm, red[i]);
        bcast = mm;
    }
    __syncthreads();
    m = bcast;
    __syncthreads();

    float z = 0.f;
    for (int t = s0 + tid; t < s1; t += 256) z += __expf(g_logits[t] - m);
#pragma unroll
    for (int o = 16; o; o >>= 1) z += __shfl_xor_sync(0xffffffffu, z, o);
    if ((tid & 31) == 0) red[tid >> 5] = z;
    __syncthreads();
    if (tid == 0) {
        float zz = 0.f;
#pragma unroll
        for (int i = 0; i < 8; i++) zz += red[i];
        bcast = zz;
    }
    __syncthreads();
    const float inv = 1.f / bcast;
    __syncthreads();

    for (int t = s0 + tid; t < s1; t += 256) wout[t] = __expf(g_logits[t] - m) * inv;
    __syncthreads();

    float acc = 0.f;
    for (int t = s0; t < s1; t++) {
        float w = wout[t];
        acc = fmaf(w, g_kv[(size_t)t * KV_DIM + H_DIM + tid], acc);
    }
    emb[(size_t)s * H_DIM + tid] = acc;
}

// ---------------------------------------------------------------------------
// Launch
// ---------------------------------------------------------------------------
extern "C" void kernel_launch(void* const* d_in, const int* in_sizes, int n_in,
                              void* d_out, int out_size)
{
    const float* objects = (const float*)d_in[0];
    const float* context = (const float*)d_in[1];
    const int*   seg     = (const int*)  d_in[2];
    const float* W1 = (const float*)d_in[3];
    const float* b1 = (const float*)d_in[4];
    const float* W2 = (const float*)d_in[5];
    const float* b2 = (const float*)d_in[6];
    const float* W3 = (const float*)d_in[7];
    const float* b3 = (const float*)d_in[8];
    const float* Wq = (const float*)d_in[9];
    const float* bq = (const float*)d_in[10];

    const int T = in_sizes[2];                 // 262144
    const int B = in_sizes[1] / C_DIM;         // 4096

    float* out = (float*)d_out;
    float* emb_out = out;
    float* w_out   = out + (size_t)B * H_DIM;

    float *p_h1, *p_h2, *p_kv, *p_q, *p_w1, *p_w2, *p_w3, *p_wq;
    cudaGetSymbolAddress((void**)&p_h1, g_h1);
    cudaGetSymbolAddress((void**)&p_h2, g_h2);
    cudaGetSymbolAddress((void**)&p_kv, g_kv);
    cudaGetSymbolAddress((void**)&p_q,  g_q);
    cudaGetSymbolAddress((void**)&p_w1, g_Wt1);
    cudaGetSymbolAddress((void**)&p_w2, g_Wt2);
    cudaGetSymbolAddress((void**)&p_w3, g_Wt3);
    cudaGetSymbolAddress((void**)&p_wq, g_Wtq);

    // Transpose + round weights to K-major [N][K] tf32
    transpose_round<<<(F_DIM * H_DIM + 255) / 256, 256>>>(W1, p_w1, F_DIM, H_DIM);
    transpose_round<<<(H_DIM * H_DIM + 255) / 256, 256>>>(W2, p_w2, H_DIM, H_DIM);
    transpose_round<<<(H_DIM * KV_DIM + 255) / 256, 256>>>(W3, p_w3, H_DIM, KV_DIM);
    transpose_round<<<(C_DIM * H_DIM + 255) / 256, 256>>>(Wq, p_wq, C_DIM, H_DIM);

    // q = context @ Wq + bq       [4096, 512] -> [4096, 256]   (cvt A in-reg)
    gemm_tc<false, false, true ><<<dim3(H_DIM / 128, B / 128), 256>>>(context, p_wq, bq, p_q, B, H_DIM, C_DIM);
    // h1 = relu(objects @ W1 + b1)  [T,128] -> [T,256]  (cvt A, round store)
    gemm_tc<true,  true,  true ><<<dim3(H_DIM / 128, T / 128), 256>>>(objects, p_w1, b1, p_h1, T, H_DIM, F_DIM);
    // h2 = relu(h1 @ W2 + b2)       [T,256] -> [T,256]  (A already tf32)
    gemm_tc<true,  true,  false><<<dim3(H_DIM / 128, T / 128), 256>>>(p_h1, p_w2, b2, p_h2, T, H_DIM, H_DIM);
    // kv = h2 @ W3 + b3             [T,256] -> [T,512]  (full fp32 out)
    gemm_tc<false, false, false><<<dim3(KV_DIM / 128, T / 128), 256>>>(p_h2, p_w3, b3, p_kv, T, KV_DIM, H_DIM);

    segstart_kernel<<<(T + 255) / 256, 256>>>(seg, T, B);
    logits_kernel<<<T / 8, 256>>>(seg, T);
    segreduce_kernel<<<B, 256>>>(emb_out, w_out);
}

// round 4
// speedup vs baseline: 5.1269x; 1.5416x over previous
#include <cuda_runtime.h>
#include <cuda_fp16.h>
#include <math.h>
#include <stdint.h>

// Problem shapes (fixed by the dataset)
#define T_MAX 262144
#define B_MAX 4096
#define F_DIM 128
#define H_DIM 256
#define C_DIM 512
#define KV_DIM 512

// ---------------------------------------------------------------------------
// Scratch (allocation-free rule: __device__ globals)
// ---------------------------------------------------------------------------
__device__ __half g_objh[(size_t)T_MAX * F_DIM];      // 64 MB
__device__ __half g_ctxh[(size_t)B_MAX * C_DIM];      // 4 MB
__device__ __half g_h1 [(size_t)T_MAX * H_DIM];       // 128 MB
__device__ __half g_h2 [(size_t)T_MAX * H_DIM];       // 128 MB
__device__ __half g_k  [(size_t)T_MAX * H_DIM];       // 128 MB (k half of kv)
__device__ float  g_v  [(size_t)T_MAX * H_DIM];       // 256 MB (v half of kv)
__device__ float  g_q  [(size_t)B_MAX * H_DIM];       // 4 MB
__device__ __half g_Wt1[H_DIM * F_DIM];               // W1^T [N][K] fp16
__device__ __half g_Wt2[H_DIM * H_DIM];
__device__ __half g_Wt3[KV_DIM * H_DIM];
__device__ __half g_Wtq[H_DIM * C_DIM];
__device__ float  g_logits[T_MAX];
__device__ int    g_segstart[B_MAX + 1];

// ---------------------------------------------------------------------------
// Helpers
// ---------------------------------------------------------------------------
__device__ __forceinline__ uint32_t smem_u32(const void* p) {
    uint32_t a;
    asm("{ .reg .u64 t; cvta.to.shared.u64 t, %1; cvt.u32.u64 %0, t; }" : "=r"(a) : "l"(p));
    return a;
}

#define CP_ASYNC16(dst, src) \
    asm volatile("cp.async.cg.shared.global [%0], [%1], 16;" :: "r"(dst), "l"(src) : "memory")
#define CP_COMMIT() asm volatile("cp.async.commit_group;" ::: "memory")
#define CP_WAIT0()  asm volatile("cp.async.wait_group 0;" ::: "memory")
#define CP_WAIT1()  asm volatile("cp.async.wait_group 1;" ::: "memory")

// mma.sync m16n8k16 fp16 -> fp32 accumulate
__device__ __forceinline__ void mma_fp16(float* c, const uint32_t* a, const uint32_t* b) {
    asm volatile(
        "mma.sync.aligned.m16n8k16.row.col.f32.f16.f16.f32 "
        "{%0,%1,%2,%3}, {%4,%5,%6,%7}, {%8,%9}, {%0,%1,%2,%3};"
        : "+f"(c[0]), "+f"(c[1]), "+f"(c[2]), "+f"(c[3])
        : "r"(a[0]), "r"(a[1]), "r"(a[2]), "r"(a[3]), "r"(b[0]), "r"(b[1]));
}

// ---------------------------------------------------------------------------
// fp16 tensor-core GEMM: C[M,N] = A[M,K] @ Wt[N,K]^T + bias
// BM=128, BN=128, BK=32 (fp16), 256 threads, warp tile 32x64, 2-stage cp.async.
// SMEM rows stride 40 halves (20 u32) -> conflict-free u32 fragment loads.
// MODE: 0 = fp32 out, 1 = fp16 out (+optional relu), 2 = kv split (k fp16 / v fp32)
// ---------------------------------------------------------------------------
#define ST_H 40                               // halves per smem row
#define ST_U 20                               // u32 per smem row
#define STAGE_U32 (2 * 128 * ST_U)            // A + B per stage, in u32

template <bool RELU, int MODE>
__global__ __launch_bounds__(256, 2) void gemm_fp16(
    const __half* __restrict__ A, const __half* __restrict__ Wt,
    const float* __restrict__ bias,
    float* __restrict__ Cf, __half* __restrict__ Ch,
    float* __restrict__ Vf,                   // MODE 2 only
    int M, int N, int K)
{
    __shared__ uint32_t sm[2 * STAGE_U32];    // 40960 B
    const uint32_t sb = smem_u32(sm);

    const int tid  = threadIdx.x;
    const int wid  = tid >> 5;
    const int lane = tid & 31;
    const int g    = lane >> 2;               // 0..7
    const int tg   = lane & 3;                // 0..3
    const int wm   = wid >> 1;                // 0..3
    const int wn   = wid & 1;                 // 0..1

    const size_t m0 = (size_t)blockIdx.y * 128;
    const size_t n0 = (size_t)blockIdx.x * 128;
    const __half* Ablk = A  + m0 * K;
    const __half* Bblk = Wt + n0 * K;

    auto load_stage = [&](int s, int kblk) {
        const __half* Asrc = Ablk + kblk * 32;
        const __half* Bsrc = Bblk + kblk * 32;
        uint32_t abase = sb + (uint32_t)(s * STAGE_U32) * 4u;
        uint32_t bbase = abase + 128 * ST_U * 4u;
#pragma unroll
        for (int i = 0; i < 2; i++) {
            int idx = tid + i * 256;
            int row = idx >> 2, k8 = idx & 3;   // 8 halves per 16B chunk
            CP_ASYNC16(abase + (uint32_t)(row * 80 + k8 * 16),
                       Asrc + (size_t)row * K + k8 * 8);
            CP_ASYNC16(bbase + (uint32_t)(row * 80 + k8 * 16),
                       Bsrc + (size_t)row * K + k8 * 8);
        }
        CP_COMMIT();
    };

    float acc[2][8][4];
#pragma unroll
    for (int mf = 0; mf < 2; mf++)
#pragma unroll
        for (int nf = 0; nf < 8; nf++)
#pragma unroll
            for (int j = 0; j < 4; j++) acc[mf][nf][j] = 0.f;

    const int nk = K >> 5;
    load_stage(0, 0);

    for (int c = 0; c < nk; c++) {
        if (c + 1 < nk) { load_stage((c + 1) & 1, c + 1); CP_WAIT1(); }
        else            { CP_WAIT0(); }
        __syncthreads();

        const uint32_t* As = sm + (c & 1) * STAGE_U32;
        const uint32_t* Bs = As + 128 * ST_U;

#pragma unroll
        for (int ks = 0; ks < 2; ks++) {       // two k16 steps per BK=32
            uint32_t a[2][4], b[8][2];
#pragma unroll
            for (int mf = 0; mf < 2; mf++) {
                int r = wm * 32 + mf * 16 + g;
                int kb = ks * 8 + tg;          // u32 index within row
                a[mf][0] = As[r * ST_U + kb];
                a[mf][1] = As[(r + 8) * ST_U + kb];
                a[mf][2] = As[r * ST_U + kb + 4];
                a[mf][3] = As[(r + 8) * ST_U + kb + 4];
            }
#pragma unroll
            for (int nf = 0; nf < 8; nf++) {
                int n = wn * 64 + nf * 8 + g;
                int kb = ks * 8 + tg;
                b[nf][0] = Bs[n * ST_U + kb];
                b[nf][1] = Bs[n * ST_U + kb + 4];
            }
#pragma unroll
            for (int mf = 0; mf < 2; mf++)
#pragma unroll
                for (int nf = 0; nf < 8; nf++)
                    mma_fp16(acc[mf][nf], a[mf], b[nf]);
        }
        __syncthreads();
    }

    // Epilogue
#pragma unroll
    for (int mf = 0; mf < 2; mf++) {
        size_t row0 = m0 + wm * 32 + mf * 16 + g;
#pragma unroll
        for (int nf = 0; nf < 8; nf++) {
            int col = (int)n0 + wn * 64 + nf * 8 + tg * 2;
            float b0 = bias[col], b1 = bias[col + 1];
            float v0 = acc[mf][nf][0] + b0;
            float v1 = acc[mf][nf][1] + b1;
            float v2 = acc[mf][nf][2] + b0;
            float v3 = acc[mf][nf][3] + b1;
            if (RELU) { v0 = fmaxf(v0, 0.f); v1 = fmaxf(v1, 0.f); v2 = fmaxf(v2, 0.f); v3 = fmaxf(v3, 0.f); }
            if (MODE == 0) {
                *reinterpret_cast<float2*>(Cf + row0 * N + col)       = make_float2(v0, v1);
                *reinterpret_cast<float2*>(Cf + (row0 + 8) * N + col) = make_float2(v2, v3);
            } else if (MODE == 1) {
                *reinterpret_cast<__half2*>(Ch + row0 * N + col)       = __floats2half2_rn(v0, v1);
                *reinterpret_cast<__half2*>(Ch + (row0 + 8) * N + col) = __floats2half2_rn(v2, v3);
            } else {
                // kv split: cols [0,256) -> k (fp16), cols [256,512) -> v (fp32)
                if (col < 256) {
                    *reinterpret_cast<__half2*>(Ch + row0 * 256 + col)       = __floats2half2_rn(v0, v1);
                    *reinterpret_cast<__half2*>(Ch + (row0 + 8) * 256 + col) = __floats2half2_rn(v2, v3);
                } else {
                    int vc = col - 256;
                    *reinterpret_cast<float2*>(Vf + row0 * 256 + vc)       = make_float2(v0, v1);
                    *reinterpret_cast<float2*>(Vf + (row0 + 8) * 256 + vc) = make_float2(v2, v3);
                }
            }
        }
    }
}

// ---------------------------------------------------------------------------
// Prep kernels
// ---------------------------------------------------------------------------
__global__ void cvt_fp16(const float* __restrict__ in, __half* __restrict__ out, int n4) {
    int i = blockIdx.x * 256 + threadIdx.x;
    if (i < n4) {
        float4 v = reinterpret_cast<const float4*>(in)[i];
        __half2 h0 = __floats2half2_rn(v.x, v.y);
        __half2 h1 = __floats2half2_rn(v.z, v.w);
        reinterpret_cast<__half2*>(out)[i * 2]     = h0;
        reinterpret_cast<__half2*>(out)[i * 2 + 1] = h1;
    }
}

__global__ void transpose_cvt(const float* __restrict__ W, __half* __restrict__ Wt, int K, int N) {
    int i = blockIdx.x * 256 + threadIdx.x;
    if (i < K * N) {
        int k = i / N, n = i - k * N;
        Wt[(size_t)n * K + k] = __float2half_rn(W[i]);
    }
}

// ---------------------------------------------------------------------------
// Segment starts from sorted segment_ids (every segment non-empty).
// ---------------------------------------------------------------------------
__global__ void segstart_kernel(const int* __restrict__ seg, int T, int B)
{
    int t = blockIdx.x * 256 + threadIdx.x;
    if (t == 0) { g_segstart[seg[0]] = 0; g_segstart[B] = T; }
    if (t > 0 && t < T) {
        int s = seg[t];
        if (s != seg[t - 1]) g_segstart[s] = t;
    }
}

// logits[t] = dot(q[seg[t]], k[t]) / 16   (warp per row, fp16 k)
__global__ __launch_bounds__(256) void logits_kernel(const int* __restrict__ seg, int T)
{
    int t = blockIdx.x * 8 + (threadIdx.x >> 5);
    if (t >= T) return;
    int lane = threadIdx.x & 31;
    const __half2* krow = reinterpret_cast<const __half2*>(g_k + (size_t)t * H_DIM);
    const float* qrow = g_q + (size_t)seg[t] * H_DIM;
    float s = 0.f;
#pragma unroll
    for (int i = lane; i < H_DIM / 2; i += 32) {
        float2 kf = __half22float2(krow[i]);
        s = fmaf(kf.x, qrow[i * 2], s);
        s = fmaf(kf.y, qrow[i * 2 + 1], s);
    }
#pragma unroll
    for (int o = 16; o; o >>= 1) s += __shfl_xor_sync(0xffffffffu, s, o);
    if (lane == 0) g_logits[t] = s * 0.0625f;
}

// Per-segment softmax + weighted value sum. One 256-thread block per segment.
__global__ __launch_bounds__(256) void segreduce_kernel(
    float* __restrict__ emb, float* __restrict__ wout)
{
    const int s = blockIdx.x;
    const int s0 = g_segstart[s];
    const int s1 = g_segstart[s + 1];
    const int tid = threadIdx.x;

    __shared__ float red[8];
    __shared__ float bcast;

    float m = -INFINITY;
    for (int t = s0 + tid; t < s1; t += 256) m = fmaxf(m, g_logits[t]);
#pragma unroll
    for (int o = 16; o; o >>= 1) m = fmaxf(m, __shfl_xor_sync(0xffffffffu, m, o));
    if ((tid & 31) == 0) red[tid >> 5] = m;
    __syncthreads();
    if (tid == 0) {
        float mm = red[0];
#pragma unroll
        for (int i = 1; i < 8; i++) mm = fmaxf(mm, red[i]);
        bcast = mm;
    }
    __syncthreads();
    m = bcast;
    __syncthreads();

    float z = 0.f;
    for (int t = s0 + tid; t < s1; t += 256) z += __expf(g_logits[t] - m);
#pragma unroll
    for (int o = 16; o; o >>= 1) z += __shfl_xor_sync(0xffffffffu, z, o);
    if ((tid & 31) == 0) red[tid >> 5] = z;
    __syncthreads();
    if (tid == 0) {
        float zz = 0.f;
#pragma unroll
        for (int i = 0; i < 8; i++) zz += red[i];
        bcast = zz;
    }
    __syncthreads();
    const float inv = 1.f / bcast;
    __syncthreads();

    for (int t = s0 + tid; t < s1; t += 256) wout[t] = __expf(g_logits[t] - m) * inv;
    __syncthreads();

    float acc = 0.f;
    for (int t = s0; t < s1; t++) {
        float w = wout[t];
        acc = fmaf(w, g_v[(size_t)t * H_DIM + tid], acc);
    }
    emb[(size_t)s * H_DIM + tid] = acc;
}

// ---------------------------------------------------------------------------
// Launch
// ---------------------------------------------------------------------------
extern "C" void kernel_launch(void* const* d_in, const int* in_sizes, int n_in,
                              void* d_out, int out_size)
{
    const float* objects = (const float*)d_in[0];
    const float* context = (const float*)d_in[1];
    const int*   seg     = (const int*)  d_in[2];
    const float* W1 = (const float*)d_in[3];
    const float* b1 = (const float*)d_in[4];
    const float* W2 = (const float*)d_in[5];
    const float* b2 = (const float*)d_in[6];
    const float* W3 = (const float*)d_in[7];
    const float* b3 = (const float*)d_in[8];
    const float* Wq = (const float*)d_in[9];
    const float* bq = (const float*)d_in[10];

    const int T = in_sizes[2];                 // 262144
    const int B = in_sizes[1] / C_DIM;         // 4096

    float* out = (float*)d_out;
    float* emb_out = out;
    float* w_out   = out + (size_t)B * H_DIM;

    __half *p_objh, *p_ctxh, *p_h1, *p_h2, *p_k, *p_w1, *p_w2, *p_w3, *p_wq;
    float *p_v, *p_q;
    cudaGetSymbolAddress((void**)&p_objh, g_objh);
    cudaGetSymbolAddress((void**)&p_ctxh, g_ctxh);
    cudaGetSymbolAddress((void**)&p_h1, g_h1);
    cudaGetSymbolAddress((void**)&p_h2, g_h2);
    cudaGetSymbolAddress((void**)&p_k,  g_k);
    cudaGetSymbolAddress((void**)&p_v,  g_v);
    cudaGetSymbolAddress((void**)&p_q,  g_q);
    cudaGetSymbolAddress((void**)&p_w1, g_Wt1);
    cudaGetSymbolAddress((void**)&p_w2, g_Wt2);
    cudaGetSymbolAddress((void**)&p_w3, g_Wt3);
    cudaGetSymbolAddress((void**)&p_wq, g_Wtq);

    // Convert inputs to fp16
    cvt_fp16<<<(T * F_DIM / 4 + 255) / 256, 256>>>(objects, p_objh, T * F_DIM / 4);
    cvt_fp16<<<(B * C_DIM / 4 + 255) / 256, 256>>>(context, p_ctxh, B * C_DIM / 4);
    // Transpose + convert weights to K-major [N][K] fp16
    transpose_cvt<<<(F_DIM * H_DIM + 255) / 256, 256>>>(W1, p_w1, F_DIM, H_DIM);
    transpose_cvt<<<(H_DIM * H_DIM + 255) / 256, 256>>>(W2, p_w2, H_DIM, H_DIM);
    transpose_cvt<<<(H_DIM * KV_DIM + 255) / 256, 256>>>(W3, p_w3, H_DIM, KV_DIM);
    transpose_cvt<<<(C_DIM * H_DIM + 255) / 256, 256>>>(Wq, p_wq, C_DIM, H_DIM);

    // q = context @ Wq + bq  [4096,512]->[4096,256] fp32 out
    gemm_fp16<false, 0><<<dim3(H_DIM / 128, B / 128), 256>>>(
        p_ctxh, p_wq, bq, p_q, nullptr, nullptr, B, H_DIM, C_DIM);
    // h1 = relu(objects @ W1 + b1)  fp16 out
    gemm_fp16<true, 1><<<dim3(H_DIM / 128, T / 128), 256>>>(
        p_objh, p_w1, b1, nullptr, p_h1, nullptr, T, H_DIM, F_DIM);
    // h2 = relu(h1 @ W2 + b2)  fp16 out
    gemm_fp16<true, 1><<<dim3(H_DIM / 128, T / 128), 256>>>(
        p_h1, p_w2, b2, nullptr, p_h2, nullptr, T, H_DIM, H_DIM);
    // kv = h2 @ W3 + b3  -> k fp16, v fp32
    gemm_fp16<false, 2><<<dim3(KV_DIM / 128, T / 128), 256>>>(
        p_h2, p_w3, b3, nullptr, p_k, p_v, T, KV_DIM, H_DIM);

    segstart_kernel<<<(T + 255) / 256, 256>>>(seg, T, B);
    logits_kernel<<<T / 8, 256>>>(seg, T);
    segreduce_kernel<<<B, 256>>>(emb_out, w_out);
}